// round 4
// baseline (speedup 1.0000x reference)
#include <cuda_runtime.h>
#include <cuda_fp16.h>
#include <cstdint>

// ---------------- problem constants ----------------
#define M_TOTAL   4096
#define K_TOTAL   4096
#define N_TOTAL   11008

#define BM        128
#define BN        256
#define BK        64                  // fp16 per K chunk (128 B/row)
#define NKIT      (K_TOTAL / BK)      // 64
#define MT_TILES  (M_TOTAL / BM)      // 32
#define NT_TILES  (N_TOTAL / BN)      // 43
#define NTILES    (MT_TILES * NT_TILES)  // 1376
#define STAGES    4

#define A_STAGE_BYTES (BM * 128)                        // 16384
#define B_STAGE_BYTES (BN * 128)                        // 32768
#define STAGE_BYTES   (A_STAGE_BYTES + B_STAGE_BYTES)   // 49152
#define SMEM_BYTES    (STAGES * STAGE_BYTES)            // 196608

// ---------------- device scratch ----------------
static __device__ __align__(16) __half g_xh[(size_t)M_TOTAL * K_TOTAL];   // ~34 MB
static __device__ __align__(16) __half g_w [(size_t)N_TOTAL * K_TOTAL];   // ~90 MB
static __device__ int g_ctr;

// ---------------- helpers ----------------
#define SWZ(off) ((off) ^ (((off) >> 3) & 0x70))

__device__ __forceinline__ uint32_t smem_u32(const void* p) {
    uint32_t a;
    asm("{ .reg .u64 t; cvta.to.shared.u64 t, %1; cvt.u32.u64 %0, t; }" : "=r"(a) : "l"(p));
    return a;
}

#define CP_ASYNC16(dst_u32, src_ptr) \
    asm volatile("cp.async.cg.shared.global [%0], [%1], 16;" :: "r"(dst_u32), "l"(src_ptr))
#define CP_COMMIT() asm volatile("cp.async.commit_group;" ::: "memory")
#define CP_WAIT2()  asm volatile("cp.async.wait_group 2;" ::: "memory")
#define CP_WAIT0()  asm volatile("cp.async.wait_group 0;" ::: "memory")

#define LDSM_X4(r0, r1, r2, r3, addr) \
    asm volatile("ldmatrix.sync.aligned.m8n8.x4.shared.b16 {%0,%1,%2,%3}, [%4];" \
                 : "=r"(r0), "=r"(r1), "=r"(r2), "=r"(r3) : "r"(addr))

#define MMA16816(c, a, b) \
    asm volatile("mma.sync.aligned.m16n8k16.row.col.f32.f16.f16.f32 " \
                 "{%0,%1,%2,%3}, {%4,%5,%6,%7}, {%8,%9}, {%0,%1,%2,%3};" \
                 : "+f"((c)[0]), "+f"((c)[1]), "+f"((c)[2]), "+f"((c)[3]) \
                 : "r"((a)[0]), "r"((a)[1]), "r"((a)[2]), "r"((a)[3]), \
                   "r"((b)[0]), "r"((b)[1]))

// ---------------- prep kernels ----------------
__global__ void k_convert_x(const float* __restrict__ x) {
    if (blockIdx.x == 0 && threadIdx.x == 0) g_ctr = 0;   // reset persistent-tile counter
    size_t i = ((size_t)blockIdx.x * blockDim.x + threadIdx.x) * 8;
    float4 a = *(const float4*)(x + i);
    float4 b = *(const float4*)(x + i + 4);
    __half2 h0 = __floats2half2_rn(a.x, a.y);
    __half2 h1 = __floats2half2_rn(a.z, a.w);
    __half2 h2 = __floats2half2_rn(b.x, b.y);
    __half2 h3 = __floats2half2_rn(b.z, b.w);
    uint4 o;
    o.x = *(uint32_t*)&h0; o.y = *(uint32_t*)&h1;
    o.z = *(uint32_t*)&h2; o.w = *(uint32_t*)&h3;
    *(uint4*)(g_xh + i) = o;
}

__device__ __forceinline__ uint32_t dq_pair(int v) {
    int lo = (v & 15) - 8;
    int hi = ((v >> 4) & 15) - 8;
    __half2 h = __floats2half2_rn((float)lo, (float)hi);
    return *(uint32_t*)&h;
}

__global__ void k_dequant(const int* __restrict__ wp) {
    size_t i = ((size_t)blockIdx.x * blockDim.x + threadIdx.x) * 4;
    int4 v = *(const int4*)(wp + i);
    uint4 o;
    o.x = dq_pair(v.x); o.y = dq_pair(v.y);
    o.z = dq_pair(v.z); o.w = dq_pair(v.w);
    *(uint4*)(g_w + 2 * i) = o;
}

// ---------------- persistent GEMM kernel ----------------
__global__ __launch_bounds__(256, 1) void k_gemm(const float* __restrict__ scale,
                                                 const float* __restrict__ bias,
                                                 float* __restrict__ out) {
    extern __shared__ __align__(1024) char smem[];
    __shared__ int s_tile;

    const int tid  = threadIdx.x;
    const int wid  = tid >> 5;
    const int lane = tid & 31;

    // warp layout: 2 (M) x 4 (N), warp tile 64x64
    const int wm0 = (wid & 1) * 64;
    const int wn0 = (wid >> 1) * 64;

    const uint32_t sb = smem_u32(smem);
    const int ac8  = tid & 7;
    const int lrow = lane & 15;
    const int lchk = lane >> 4;

    for (;;) {
        if (tid == 0) s_tile = atomicAdd(&g_ctr, 1);
        __syncthreads();
        const int t = s_tile;
        if (t >= NTILES) break;

        const int mt = t % MT_TILES;        // mt fastest -> B tile L2-shared across wave
        const int nt = t / MT_TILES;
        const int m0 = mt * BM;
        const int n0 = nt * BN;

        float acc[4][8][4];
        #pragma unroll
        for (int i = 0; i < 4; ++i)
            #pragma unroll
            for (int j = 0; j < 8; ++j)
                #pragma unroll
                for (int k = 0; k < 4; ++k) acc[i][j][k] = 0.f;

        auto load_stage = [&](int kc, int s) {
            const uint32_t sA = sb + s * STAGE_BYTES;
            const uint32_t sB = sA + A_STAGE_BYTES;
            const __half* gA = g_xh + (size_t)m0 * K_TOTAL + kc * BK;
            const __half* gB = g_w  + (size_t)n0 * K_TOTAL + kc * BK;
            #pragma unroll
            for (int tt = 0; tt < 4; ++tt) {
                int row = (tid + tt * 256) >> 3;
                CP_ASYNC16(sA + SWZ(row * 128 + ac8 * 16),
                           gA + (size_t)row * K_TOTAL + ac8 * 8);
            }
            #pragma unroll
            for (int tt = 0; tt < 8; ++tt) {
                int row = (tid + tt * 256) >> 3;
                CP_ASYNC16(sB + SWZ(row * 128 + ac8 * 16),
                           gB + (size_t)row * K_TOTAL + ac8 * 8);
            }
        };

        load_stage(0, 0); CP_COMMIT();
        load_stage(1, 1); CP_COMMIT();
        load_stage(2, 2); CP_COMMIT();

        // fragment ping-pong buffers
        uint32_t afr[2][4][4];
        uint32_t bfr[2][8][2];

        auto load_frags = [&](uint32_t sA, uint32_t sB, int ks, int buf) {
            #pragma unroll
            for (int mti = 0; mti < 4; ++mti) {
                int row = wm0 + mti * 16 + lrow;
                LDSM_X4(afr[buf][mti][0], afr[buf][mti][1],
                        afr[buf][mti][2], afr[buf][mti][3],
                        sA + SWZ(row * 128 + (2 * ks + lchk) * 16));
            }
            #pragma unroll
            for (int np = 0; np < 4; ++np) {
                int row = wn0 + np * 16 + lrow;
                uint32_t r0, r1, r2, r3;
                LDSM_X4(r0, r1, r2, r3,
                        sB + SWZ(row * 128 + (2 * ks + lchk) * 16));
                bfr[buf][2 * np + 0][0] = r0; bfr[buf][2 * np + 0][1] = r2;
                bfr[buf][2 * np + 1][0] = r1; bfr[buf][2 * np + 1][1] = r3;
            }
        };

        for (int it = 0; it < NKIT; ++it) {
            CP_WAIT2();
            __syncthreads();

            const uint32_t sA = sb + (it & 3) * STAGE_BYTES;
            const uint32_t sB = sA + A_STAGE_BYTES;

            // critical path first: fragments for ks=0
            load_frags(sA, sB, 0, 0);

            // then enqueue the global->smem stage for it+3
            if (it + 3 < NKIT) load_stage(it + 3, (it + 3) & 3);
            CP_COMMIT();

            #pragma unroll
            for (int ks = 0; ks < 4; ++ks) {
                const int cur = ks & 1;
                if (ks < 3) load_frags(sA, sB, ks + 1, cur ^ 1);
                #pragma unroll
                for (int mti = 0; mti < 4; ++mti)
                    #pragma unroll
                    for (int nti = 0; nti < 8; ++nti)
                        MMA16816(acc[mti][nti], afr[cur][mti], bfr[cur][nti]);
            }
        }
        CP_WAIT0();

        // ---------------- epilogue ----------------
        {
            const int row_base = m0 + wm0;
            const int col_base = n0 + wn0;
            const int r_in = lane >> 2;
            const int c_in = (lane & 3) * 2;

            #pragma unroll
            for (int nti = 0; nti < 8; ++nti) {
                const int c = col_base + nti * 8 + c_in;
                const float2 sc = *(const float2*)(scale + c);
                const float2 bi = *(const float2*)(bias + c);
                #pragma unroll
                for (int mti = 0; mti < 4; ++mti) {
                    const int r0 = row_base + mti * 16 + r_in;
                    float2 v0, v1;
                    v0.x = acc[mti][nti][0] * sc.x + bi.x;
                    v0.y = acc[mti][nti][1] * sc.y + bi.y;
                    v1.x = acc[mti][nti][2] * sc.x + bi.x;
                    v1.y = acc[mti][nti][3] * sc.y + bi.y;
                    *(float2*)(out + (size_t)r0 * N_TOTAL + c)       = v0;
                    *(float2*)(out + (size_t)(r0 + 8) * N_TOTAL + c) = v1;
                }
            }
        }
    }
}

// ---------------- launch ----------------
extern "C" void kernel_launch(void* const* d_in, const int* in_sizes, int n_in,
                              void* d_out, int out_size) {
    const float* x   = (const float*)d_in[0];
    const int*   wp  = (const int*)d_in[1];
    const float* scl = (const float*)d_in[2];
    const float* bia = (const float*)d_in[3];
    float* out = (float*)d_out;

    cudaFuncSetAttribute(k_gemm, cudaFuncAttributeMaxDynamicSharedMemorySize, SMEM_BYTES);

    k_convert_x<<<8192, 256>>>(x);           // also resets g_ctr
    k_dequant<<<22016, 256>>>(wp);
    k_gemm<<<148, 256, SMEM_BYTES>>>(scl, bia, out);
}

// round 5
// speedup vs baseline: 1.0480x; 1.0480x over previous
#include <cuda_runtime.h>
#include <cuda_fp16.h>
#include <cstdint>

// ---------------- problem constants ----------------
#define M_TOTAL   4096
#define K_TOTAL   4096
#define N_TOTAL   11008

#define BM        128
#define BN        256
#define BK        64                  // fp16 per K chunk (128 B/row)
#define NKIT      (K_TOTAL / BK)      // 64
#define MT_TILES  (M_TOTAL / BM)      // 32
#define NT_TILES  (N_TOTAL / BN)      // 43
#define NTILES    (MT_TILES * NT_TILES)  // 1376
#define STAGES    4
#define NTHREADS  512

#define A_STAGE_BYTES (BM * 128)                        // 16384
#define B_STAGE_BYTES (BN * 128)                        // 32768
#define STAGE_BYTES   (A_STAGE_BYTES + B_STAGE_BYTES)   // 49152
#define SMEM_BYTES    (STAGES * STAGE_BYTES)            // 196608

// ---------------- device scratch ----------------
static __device__ __align__(16) __half g_xh[(size_t)M_TOTAL * K_TOTAL];   // ~34 MB
static __device__ __align__(16) __half g_w [(size_t)N_TOTAL * K_TOTAL];   // ~90 MB
static __device__ int g_ctr;

// ---------------- helpers ----------------
#define SWZ(off) ((off) ^ (((off) >> 3) & 0x70))

__device__ __forceinline__ uint32_t smem_u32(const void* p) {
    uint32_t a;
    asm("{ .reg .u64 t; cvta.to.shared.u64 t, %1; cvt.u32.u64 %0, t; }" : "=r"(a) : "l"(p));
    return a;
}

#define CP_ASYNC16(dst_u32, src_ptr) \
    asm volatile("cp.async.cg.shared.global [%0], [%1], 16;" :: "r"(dst_u32), "l"(src_ptr))
#define CP_COMMIT() asm volatile("cp.async.commit_group;" ::: "memory")
#define CP_WAIT2()  asm volatile("cp.async.wait_group 2;" ::: "memory")
#define CP_WAIT0()  asm volatile("cp.async.wait_group 0;" ::: "memory")

#define LDSM_X4(r0, r1, r2, r3, addr) \
    asm volatile("ldmatrix.sync.aligned.m8n8.x4.shared.b16 {%0,%1,%2,%3}, [%4];" \
                 : "=r"(r0), "=r"(r1), "=r"(r2), "=r"(r3) : "r"(addr))

#define MMA16816(c, a, b) \
    asm volatile("mma.sync.aligned.m16n8k16.row.col.f32.f16.f16.f32 " \
                 "{%0,%1,%2,%3}, {%4,%5,%6,%7}, {%8,%9}, {%0,%1,%2,%3};" \
                 : "+f"((c)[0]), "+f"((c)[1]), "+f"((c)[2]), "+f"((c)[3]) \
                 : "r"((a)[0]), "r"((a)[1]), "r"((a)[2]), "r"((a)[3]), \
                   "r"((b)[0]), "r"((b)[1]))

// ---------------- fused prep kernel ----------------
// blocks [0, 8192): convert x (fp32 -> fp16), 8 elts/thread
// blocks [8192, 30208): dequant W (int4 pairs -> fp16), 4 int32/thread
__device__ __forceinline__ uint32_t dq_pair(int v) {
    int lo = (v & 15) - 8;
    int hi = ((v >> 4) & 15) - 8;
    __half2 h = __floats2half2_rn((float)lo, (float)hi);
    return *(uint32_t*)&h;
}

__global__ void k_prep(const float* __restrict__ x, const int* __restrict__ wp) {
    if (blockIdx.x == 0 && threadIdx.x == 0) g_ctr = 0;   // reset persistent-tile counter
    if (blockIdx.x < 8192) {
        size_t i = ((size_t)blockIdx.x * blockDim.x + threadIdx.x) * 8;
        float4 a = *(const float4*)(x + i);
        float4 b = *(const float4*)(x + i + 4);
        __half2 h0 = __floats2half2_rn(a.x, a.y);
        __half2 h1 = __floats2half2_rn(a.z, a.w);
        __half2 h2 = __floats2half2_rn(b.x, b.y);
        __half2 h3 = __floats2half2_rn(b.z, b.w);
        uint4 o;
        o.x = *(uint32_t*)&h0; o.y = *(uint32_t*)&h1;
        o.z = *(uint32_t*)&h2; o.w = *(uint32_t*)&h3;
        *(uint4*)(g_xh + i) = o;
    } else {
        size_t i = ((size_t)(blockIdx.x - 8192) * blockDim.x + threadIdx.x) * 4;
        int4 v = *(const int4*)(wp + i);
        uint4 o;
        o.x = dq_pair(v.x); o.y = dq_pair(v.y);
        o.z = dq_pair(v.z); o.w = dq_pair(v.w);
        *(uint4*)(g_w + 2 * i) = o;
    }
}

// ---------------- persistent GEMM kernel ----------------
// 512 threads, 16 warps in 2(M) x 8(N), warp tile 64x32
__global__ __launch_bounds__(NTHREADS, 1) void k_gemm(const float* __restrict__ scale,
                                                      const float* __restrict__ bias,
                                                      float* __restrict__ out) {
    extern __shared__ __align__(1024) char smem[];
    __shared__ int s_tile;

    const int tid  = threadIdx.x;
    const int wid  = tid >> 5;
    const int lane = tid & 31;

    const int wm0 = (wid & 1) * 64;       // warp M offset
    const int wn0 = (wid >> 1) * 32;      // warp N offset

    const uint32_t sb = smem_u32(smem);
    const int ac8  = tid & 7;
    const int lrow = lane & 15;
    const int lchk = lane >> 4;

    for (;;) {
        if (tid == 0) s_tile = atomicAdd(&g_ctr, 1);
        __syncthreads();
        const int t = s_tile;
        if (t >= NTILES) break;

        const int mt = t % MT_TILES;      // mt fastest -> B tile L2-shared across wave
        const int nt = t / MT_TILES;
        const int m0 = mt * BM;
        const int n0 = nt * BN;

        float acc[4][4][4];
        #pragma unroll
        for (int i = 0; i < 4; ++i)
            #pragma unroll
            for (int j = 0; j < 4; ++j)
                #pragma unroll
                for (int k = 0; k < 4; ++k) acc[i][j][k] = 0.f;

        auto load_stage = [&](int kc, int s) {
            const uint32_t sA = sb + s * STAGE_BYTES;
            const uint32_t sB = sA + A_STAGE_BYTES;
            const __half* gA = g_xh + (size_t)m0 * K_TOTAL + kc * BK;
            const __half* gB = g_w  + (size_t)n0 * K_TOTAL + kc * BK;
            #pragma unroll
            for (int tt = 0; tt < 2; ++tt) {        // A: 1024 chunks / 512 thr
                int row = (tid + tt * NTHREADS) >> 3;
                CP_ASYNC16(sA + SWZ(row * 128 + ac8 * 16),
                           gA + (size_t)row * K_TOTAL + ac8 * 8);
            }
            #pragma unroll
            for (int tt = 0; tt < 4; ++tt) {        // B: 2048 chunks / 512 thr
                int row = (tid + tt * NTHREADS) >> 3;
                CP_ASYNC16(sB + SWZ(row * 128 + ac8 * 16),
                           gB + (size_t)row * K_TOTAL + ac8 * 8);
            }
        };

        load_stage(0, 0); CP_COMMIT();
        load_stage(1, 1); CP_COMMIT();
        load_stage(2, 2); CP_COMMIT();

        for (int it = 0; it < NKIT; ++it) {
            CP_WAIT2();
            __syncthreads();
            if (it + 3 < NKIT) load_stage(it + 3, (it + 3) & 3);
            CP_COMMIT();

            const uint32_t sA = sb + (it & 3) * STAGE_BYTES;
            const uint32_t sB = sA + A_STAGE_BYTES;

            #pragma unroll
            for (int ks = 0; ks < 4; ++ks) {
                uint32_t a[4][4];
                #pragma unroll
                for (int mti = 0; mti < 4; ++mti) {
                    int row = wm0 + mti * 16 + lrow;
                    LDSM_X4(a[mti][0], a[mti][1], a[mti][2], a[mti][3],
                            sA + SWZ(row * 128 + (2 * ks + lchk) * 16));
                }
                uint32_t b[4][2];
                #pragma unroll
                for (int np = 0; np < 2; ++np) {
                    int row = wn0 + np * 16 + lrow;
                    uint32_t r0, r1, r2, r3;
                    LDSM_X4(r0, r1, r2, r3,
                            sB + SWZ(row * 128 + (2 * ks + lchk) * 16));
                    b[2 * np + 0][0] = r0; b[2 * np + 0][1] = r2;
                    b[2 * np + 1][0] = r1; b[2 * np + 1][1] = r3;
                }
                #pragma unroll
                for (int mti = 0; mti < 4; ++mti)
                    #pragma unroll
                    for (int nti = 0; nti < 4; ++nti)
                        MMA16816(acc[mti][nti], a[mti], b[nti]);
            }
        }
        CP_WAIT0();

        // ---------------- epilogue ----------------
        {
            const int row_base = m0 + wm0;
            const int col_base = n0 + wn0;
            const int r_in = lane >> 2;
            const int c_in = (lane & 3) * 2;

            #pragma unroll
            for (int nti = 0; nti < 4; ++nti) {
                const int c = col_base + nti * 8 + c_in;
                const float2 sc = *(const float2*)(scale + c);
                const float2 bi = *(const float2*)(bias + c);
                #pragma unroll
                for (int mti = 0; mti < 4; ++mti) {
                    const int r0 = row_base + mti * 16 + r_in;
                    float2 v0, v1;
                    v0.x = acc[mti][nti][0] * sc.x + bi.x;
                    v0.y = acc[mti][nti][1] * sc.y + bi.y;
                    v1.x = acc[mti][nti][2] * sc.x + bi.x;
                    v1.y = acc[mti][nti][3] * sc.y + bi.y;
                    *(float2*)(out + (size_t)r0 * N_TOTAL + c)       = v0;
                    *(float2*)(out + (size_t)(r0 + 8) * N_TOTAL + c) = v1;
                }
            }
        }
    }
}

// ---------------- launch ----------------
extern "C" void kernel_launch(void* const* d_in, const int* in_sizes, int n_in,
                              void* d_out, int out_size) {
    const float* x   = (const float*)d_in[0];
    const int*   wp  = (const int*)d_in[1];
    const float* scl = (const float*)d_in[2];
    const float* bia = (const float*)d_in[3];
    float* out = (float*)d_out;

    cudaFuncSetAttribute(k_gemm, cudaFuncAttributeMaxDynamicSharedMemorySize, SMEM_BYTES);

    // fused prep: 8192 convert blocks + 22016 dequant blocks
    k_prep<<<30208, 256>>>(x, wp);
    k_gemm<<<148, NTHREADS, SMEM_BYTES>>>(scl, bia, out);
}

// round 6
// speedup vs baseline: 1.1461x; 1.0936x over previous
#include <cuda_runtime.h>
#include <cuda_fp16.h>
#include <cstdint>

// ---------------- problem constants ----------------
#define M_TOTAL   4096
#define K_TOTAL   4096
#define N_TOTAL   11008

#define BM        128
#define BN        128
#define BK        64                  // fp16 per K chunk (128 B/row)
#define NKIT      (K_TOTAL / BK)      // 64
#define MT_TILES  (M_TOTAL / BM)      // 32
#define NT_TILES  (N_TOTAL / BN)      // 86
#define NTILES    (MT_TILES * NT_TILES)  // 2752
#define STAGES    3
#define NTHREADS  256

#define A_STAGE_BYTES (BM * 128)                        // 16384
#define B_STAGE_BYTES (BN * 128)                        // 16384
#define STAGE_BYTES   (A_STAGE_BYTES + B_STAGE_BYTES)   // 32768
#define SMEM_BYTES    (STAGES * STAGE_BYTES)            // 98304 -> 2 CTAs/SM

// ---------------- device scratch ----------------
static __device__ __align__(16) __half g_xh[(size_t)M_TOTAL * K_TOTAL];   // ~34 MB
static __device__ __align__(16) __half g_w [(size_t)N_TOTAL * K_TOTAL];   // ~90 MB
static __device__ int g_ctr;

// ---------------- helpers ----------------
#define SWZ(off) ((off) ^ (((off) >> 3) & 0x70))

__device__ __forceinline__ uint32_t smem_u32(const void* p) {
    uint32_t a;
    asm("{ .reg .u64 t; cvta.to.shared.u64 t, %1; cvt.u32.u64 %0, t; }" : "=r"(a) : "l"(p));
    return a;
}

#define CP_ASYNC16(dst_u32, src_ptr) \
    asm volatile("cp.async.cg.shared.global [%0], [%1], 16;" :: "r"(dst_u32), "l"(src_ptr))
#define CP_COMMIT() asm volatile("cp.async.commit_group;" ::: "memory")
#define CP_WAIT1()  asm volatile("cp.async.wait_group 1;" ::: "memory")
#define CP_WAIT0()  asm volatile("cp.async.wait_group 0;" ::: "memory")

#define LDSM_X4(r0, r1, r2, r3, addr) \
    asm volatile("ldmatrix.sync.aligned.m8n8.x4.shared.b16 {%0,%1,%2,%3}, [%4];" \
                 : "=r"(r0), "=r"(r1), "=r"(r2), "=r"(r3) : "r"(addr))

#define MMA16816(c, a, b) \
    asm volatile("mma.sync.aligned.m16n8k16.row.col.f32.f16.f16.f32 " \
                 "{%0,%1,%2,%3}, {%4,%5,%6,%7}, {%8,%9}, {%0,%1,%2,%3};" \
                 : "+f"((c)[0]), "+f"((c)[1]), "+f"((c)[2]), "+f"((c)[3]) \
                 : "r"((a)[0]), "r"((a)[1]), "r"((a)[2]), "r"((a)[3]), \
                   "r"((b)[0]), "r"((b)[1]))

// ---------------- fused prep kernel ----------------
__device__ __forceinline__ uint32_t dq_pair(int v) {
    int lo = (v & 15) - 8;
    int hi = ((v >> 4) & 15) - 8;
    __half2 h = __floats2half2_rn((float)lo, (float)hi);
    return *(uint32_t*)&h;
}

__global__ void k_prep(const float* __restrict__ x, const int* __restrict__ wp) {
    if (blockIdx.x == 0 && threadIdx.x == 0) g_ctr = 0;   // reset persistent-tile counter
    if (blockIdx.x < 8192) {
        size_t i = ((size_t)blockIdx.x * blockDim.x + threadIdx.x) * 8;
        float4 a = *(const float4*)(x + i);
        float4 b = *(const float4*)(x + i + 4);
        __half2 h0 = __floats2half2_rn(a.x, a.y);
        __half2 h1 = __floats2half2_rn(a.z, a.w);
        __half2 h2 = __floats2half2_rn(b.x, b.y);
        __half2 h3 = __floats2half2_rn(b.z, b.w);
        uint4 o;
        o.x = *(uint32_t*)&h0; o.y = *(uint32_t*)&h1;
        o.z = *(uint32_t*)&h2; o.w = *(uint32_t*)&h3;
        *(uint4*)(g_xh + i) = o;
    } else {
        size_t i = ((size_t)(blockIdx.x - 8192) * blockDim.x + threadIdx.x) * 4;
        int4 v = *(const int4*)(wp + i);
        uint4 o;
        o.x = dq_pair(v.x); o.y = dq_pair(v.y);
        o.z = dq_pair(v.z); o.w = dq_pair(v.w);
        *(uint4*)(g_w + 2 * i) = o;
    }
}

// ---------------- persistent GEMM kernel ----------------
// 256 threads, 8 warps in 2(M) x 4(N), warp tile 64x32; 2 CTAs/SM
__global__ __launch_bounds__(NTHREADS, 2) void k_gemm(const float* __restrict__ scale,
                                                      const float* __restrict__ bias,
                                                      float* __restrict__ out) {
    extern __shared__ __align__(1024) char smem[];
    __shared__ int s_tile;

    const int tid  = threadIdx.x;
    const int wid  = tid >> 5;
    const int lane = tid & 31;

    const int wm0 = (wid & 1) * 64;       // warp M offset
    const int wn0 = (wid >> 1) * 32;      // warp N offset

    const uint32_t sb = smem_u32(smem);
    const int ac8  = tid & 7;
    const int lrow = lane & 15;
    const int lchk = lane >> 4;

    for (;;) {
        if (tid == 0) s_tile = atomicAdd(&g_ctr, 1);
        __syncthreads();
        const int t = s_tile;
        if (t >= NTILES) break;

        const int mt = t % MT_TILES;      // mt fastest -> B tile L2-shared across wave
        const int nt = t / MT_TILES;
        const int m0 = mt * BM;
        const int n0 = nt * BN;

        float acc[4][4][4];
        #pragma unroll
        for (int i = 0; i < 4; ++i)
            #pragma unroll
            for (int j = 0; j < 4; ++j)
                #pragma unroll
                for (int k = 0; k < 4; ++k) acc[i][j][k] = 0.f;

        auto load_stage = [&](int kc, int s) {
            const uint32_t sA = sb + s * STAGE_BYTES;
            const uint32_t sB = sA + A_STAGE_BYTES;
            const __half* gA = g_xh + (size_t)m0 * K_TOTAL + kc * BK;
            const __half* gB = g_w  + (size_t)n0 * K_TOTAL + kc * BK;
            #pragma unroll
            for (int tt = 0; tt < 4; ++tt) {        // A: 1024 chunks / 256 thr
                int row = (tid + tt * NTHREADS) >> 3;
                CP_ASYNC16(sA + SWZ(row * 128 + ac8 * 16),
                           gA + (size_t)row * K_TOTAL + ac8 * 8);
            }
            #pragma unroll
            for (int tt = 0; tt < 4; ++tt) {        // B: 1024 chunks / 256 thr
                int row = (tid + tt * NTHREADS) >> 3;
                CP_ASYNC16(sB + SWZ(row * 128 + ac8 * 16),
                           gB + (size_t)row * K_TOTAL + ac8 * 8);
            }
        };

        load_stage(0, 0); CP_COMMIT();
        load_stage(1, 1); CP_COMMIT();

        int sidx = 0;                     // stage index of iteration `it` (mod 3)
        for (int it = 0; it < NKIT; ++it) {
            CP_WAIT1();                   // group `it` (oldest outstanding) complete
            __syncthreads();
            if (it + 2 < NKIT) {
                int s2 = sidx + 2; if (s2 >= STAGES) s2 -= STAGES;
                load_stage(it + 2, s2);
            }
            CP_COMMIT();

            const uint32_t sA = sb + sidx * STAGE_BYTES;
            const uint32_t sB = sA + A_STAGE_BYTES;

            #pragma unroll
            for (int ks = 0; ks < 4; ++ks) {
                uint32_t a[4][4];
                #pragma unroll
                for (int mti = 0; mti < 4; ++mti) {
                    int row = wm0 + mti * 16 + lrow;
                    LDSM_X4(a[mti][0], a[mti][1], a[mti][2], a[mti][3],
                            sA + SWZ(row * 128 + (2 * ks + lchk) * 16));
                }
                uint32_t b[4][2];
                #pragma unroll
                for (int np = 0; np < 2; ++np) {
                    int row = wn0 + np * 16 + lrow;
                    uint32_t r0, r1, r2, r3;
                    LDSM_X4(r0, r1, r2, r3,
                            sB + SWZ(row * 128 + (2 * ks + lchk) * 16));
                    b[2 * np + 0][0] = r0; b[2 * np + 0][1] = r2;
                    b[2 * np + 1][0] = r1; b[2 * np + 1][1] = r3;
                }
                #pragma unroll
                for (int mti = 0; mti < 4; ++mti)
                    #pragma unroll
                    for (int nti = 0; nti < 4; ++nti)
                        MMA16816(acc[mti][nti], a[mti], b[nti]);
            }
            if (++sidx == STAGES) sidx = 0;
        }
        CP_WAIT0();

        // ---------------- epilogue ----------------
        {
            const int row_base = m0 + wm0;
            const int col_base = n0 + wn0;
            const int r_in = lane >> 2;
            const int c_in = (lane & 3) * 2;

            #pragma unroll
            for (int nti = 0; nti < 4; ++nti) {
                const int c = col_base + nti * 8 + c_in;
                const float2 sc = *(const float2*)(scale + c);
                const float2 bi = *(const float2*)(bias + c);
                #pragma unroll
                for (int mti = 0; mti < 4; ++mti) {
                    const int r0 = row_base + mti * 16 + r_in;
                    float2 v0, v1;
                    v0.x = acc[mti][nti][0] * sc.x + bi.x;
                    v0.y = acc[mti][nti][1] * sc.y + bi.y;
                    v1.x = acc[mti][nti][2] * sc.x + bi.x;
                    v1.y = acc[mti][nti][3] * sc.y + bi.y;
                    *(float2*)(out + (size_t)r0 * N_TOTAL + c)       = v0;
                    *(float2*)(out + (size_t)(r0 + 8) * N_TOTAL + c) = v1;
                }
            }
        }
    }
}

// ---------------- launch ----------------
extern "C" void kernel_launch(void* const* d_in, const int* in_sizes, int n_in,
                              void* d_out, int out_size) {
    const float* x   = (const float*)d_in[0];
    const int*   wp  = (const int*)d_in[1];
    const float* scl = (const float*)d_in[2];
    const float* bia = (const float*)d_in[3];
    float* out = (float*)d_out;

    cudaFuncSetAttribute(k_gemm, cudaFuncAttributeMaxDynamicSharedMemorySize, SMEM_BYTES);

    // fused prep: 8192 convert blocks + 22016 dequant blocks
    k_prep<<<30208, 256>>>(x, wp);
    // persistent GEMM, 2 CTAs/SM
    k_gemm<<<296, NTHREADS, SMEM_BYTES>>>(scl, bia, out);
}

// round 7
// speedup vs baseline: 1.1599x; 1.0120x over previous
#include <cuda_runtime.h>
#include <cuda_fp16.h>
#include <cstdint>

// ---------------- problem constants ----------------
#define M_TOTAL   4096
#define K_TOTAL   4096
#define N_TOTAL   11008

#define BM        128
#define BN        128
#define BK        64                  // fp16 per K chunk (128 B/row)
#define NKIT      (K_TOTAL / BK)      // 64
#define MT_TILES  (M_TOTAL / BM)      // 32
#define NT_TILES  (N_TOTAL / BN)      // 86
#define NTILES    (MT_TILES * NT_TILES)  // 2752
#define STAGES    3
#define NTHREADS  256

#define A_STAGE_BYTES (BM * 128)                        // 16384
#define B_STAGE_BYTES (BN * 128)                        // 16384
#define STAGE_BYTES   (A_STAGE_BYTES + B_STAGE_BYTES)   // 32768
#define SMEM_BYTES    (STAGES * STAGE_BYTES)            // 98304 -> 2 CTAs/SM

// ---------------- device scratch ----------------
static __device__ __align__(16) __half g_xh[(size_t)M_TOTAL * K_TOTAL];   // ~34 MB
static __device__ __align__(16) __half g_w [(size_t)N_TOTAL * K_TOTAL];   // ~90 MB
static __device__ int g_ctr;

// ---------------- helpers ----------------
#define SWZ(off) ((off) ^ (((off) >> 3) & 0x70))

__device__ __forceinline__ uint32_t smem_u32(const void* p) {
    uint32_t a;
    asm("{ .reg .u64 t; cvta.to.shared.u64 t, %1; cvt.u32.u64 %0, t; }" : "=r"(a) : "l"(p));
    return a;
}

#define CP_ASYNC16(dst_u32, src_ptr) \
    asm volatile("cp.async.cg.shared.global [%0], [%1], 16;" :: "r"(dst_u32), "l"(src_ptr))
#define CP_COMMIT() asm volatile("cp.async.commit_group;" ::: "memory")
#define CP_WAIT1()  asm volatile("cp.async.wait_group 1;" ::: "memory")
#define CP_WAIT0()  asm volatile("cp.async.wait_group 0;" ::: "memory")

#define LDSM_X4(r0, r1, r2, r3, addr) \
    asm volatile("ldmatrix.sync.aligned.m8n8.x4.shared.b16 {%0,%1,%2,%3}, [%4];" \
                 : "=r"(r0), "=r"(r1), "=r"(r2), "=r"(r3) : "r"(addr))

#define MMA16816(c, a, b) \
    asm volatile("mma.sync.aligned.m16n8k16.row.col.f32.f16.f16.f32 " \
                 "{%0,%1,%2,%3}, {%4,%5,%6,%7}, {%8,%9}, {%0,%1,%2,%3};" \
                 : "+f"((c)[0]), "+f"((c)[1]), "+f"((c)[2]), "+f"((c)[3]) \
                 : "r"((a)[0]), "r"((a)[1]), "r"((a)[2]), "r"((a)[3]), \
                   "r"((b)[0]), "r"((b)[1]))

// ---------------- fused prep kernel ----------------
__device__ __forceinline__ uint32_t dq_pair(int v) {
    int lo = (v & 15) - 8;
    int hi = ((v >> 4) & 15) - 8;
    __half2 h = __floats2half2_rn((float)lo, (float)hi);
    return *(uint32_t*)&h;
}

__global__ void k_prep(const float* __restrict__ x, const int* __restrict__ wp) {
    if (blockIdx.x == 0 && threadIdx.x == 0) g_ctr = 0;   // reset persistent-tile counter
    if (blockIdx.x < 8192) {
        size_t i = ((size_t)blockIdx.x * blockDim.x + threadIdx.x) * 8;
        float4 a = *(const float4*)(x + i);
        float4 b = *(const float4*)(x + i + 4);
        __half2 h0 = __floats2half2_rn(a.x, a.y);
        __half2 h1 = __floats2half2_rn(a.z, a.w);
        __half2 h2 = __floats2half2_rn(b.x, b.y);
        __half2 h3 = __floats2half2_rn(b.z, b.w);
        uint4 o;
        o.x = *(uint32_t*)&h0; o.y = *(uint32_t*)&h1;
        o.z = *(uint32_t*)&h2; o.w = *(uint32_t*)&h3;
        *(uint4*)(g_xh + i) = o;
    } else {
        size_t i = ((size_t)(blockIdx.x - 8192) * blockDim.x + threadIdx.x) * 4;
        int4 v = *(const int4*)(wp + i);
        uint4 o;
        o.x = dq_pair(v.x); o.y = dq_pair(v.y);
        o.z = dq_pair(v.z); o.w = dq_pair(v.w);
        *(uint4*)(g_w + 2 * i) = o;
    }
}

// ---------------- persistent GEMM kernel ----------------
// 256 threads, 8 warps in 2(M) x 4(N), warp tile 64x32; 2 CTAs/SM
__global__ __launch_bounds__(NTHREADS, 2) void k_gemm(const float* __restrict__ scale,
                                                      const float* __restrict__ bias,
                                                      float* __restrict__ out) {
    extern __shared__ __align__(1024) char smem[];
    __shared__ int s_tile;

    const int tid  = threadIdx.x;
    const int wid  = tid >> 5;
    const int lane = tid & 31;

    const int wm0 = (wid & 1) * 64;       // warp M offset
    const int wn0 = (wid >> 1) * 32;      // warp N offset

    const uint32_t sb = smem_u32(smem);
    const int ac8  = tid & 7;
    const int lrow = lane & 15;
    const int lchk = lane >> 4;

    // ---- loop-invariant per-thread constants (computed ONCE) ----
    // cp.async: 4 A-chunks + 4 B-chunks per thread per stage
    uint32_t dA[4], dB[4];                 // smem dst offsets within a stage
    uint32_t oA[4], oB[4];                 // gmem element offsets within a tile row-block
    #pragma unroll
    for (int t = 0; t < 4; ++t) {
        int row = (tid + t * NTHREADS) >> 3;
        dA[t] = SWZ(row * 128 + ac8 * 16);
        dB[t] = A_STAGE_BYTES + dA[t];
        oA[t] = (uint32_t)row * K_TOTAL + ac8 * 8;   // same row pattern for A and B
        oB[t] = oA[t];
    }
    // ldmatrix row bases (per warp): addr = stage_base + rb + ((2ks+lchk)^r7)*16
    uint32_t rbA[4], r7A[4];
    #pragma unroll
    for (int mti = 0; mti < 4; ++mti) {
        int row = wm0 + mti * 16 + lrow;
        rbA[mti] = (uint32_t)row * 128;
        r7A[mti] = (uint32_t)(row & 7);
    }
    uint32_t rbB[2], r7B[2];
    #pragma unroll
    for (int np = 0; np < 2; ++np) {
        int row = wn0 + np * 16 + lrow;
        rbB[np] = A_STAGE_BYTES + (uint32_t)row * 128;
        r7B[np] = (uint32_t)(row & 7);
    }

    for (;;) {
        if (tid == 0) s_tile = atomicAdd(&g_ctr, 1);
        __syncthreads();
        const int t = s_tile;
        if (t >= NTILES) break;

        const int mt = t % MT_TILES;      // mt fastest -> B tile L2-shared across wave
        const int nt = t / MT_TILES;
        const int m0 = mt * BM;
        const int n0 = nt * BN;

        float acc[4][4][4];
        #pragma unroll
        for (int i = 0; i < 4; ++i)
            #pragma unroll
            for (int j = 0; j < 4; ++j)
                #pragma unroll
                for (int k = 0; k < 4; ++k) acc[i][j][k] = 0.f;

        // per-tile incrementing gmem base pointers (advance 128 B per stage)
        const char* gAp = (const char*)(g_xh + (size_t)m0 * K_TOTAL);
        const char* gBp = (const char*)(g_w  + (size_t)n0 * K_TOTAL);

        auto load_stage = [&](int s) {
            const uint32_t base = sb + s * STAGE_BYTES;
            #pragma unroll
            for (int tt = 0; tt < 4; ++tt)
                CP_ASYNC16(base + dA[tt], gAp + (size_t)oA[tt] * 2);
            #pragma unroll
            for (int tt = 0; tt < 4; ++tt)
                CP_ASYNC16(base + dB[tt], gBp + (size_t)oB[tt] * 2);
            gAp += BK * 2;                 // next K chunk
            gBp += BK * 2;
        };

        load_stage(0); CP_COMMIT();
        load_stage(1); CP_COMMIT();

        int sidx = 0;                     // stage of iteration `it`
        int sld  = 2;                     // stage to load next
        for (int it = 0; it < NKIT; ++it) {
            CP_WAIT1();                   // oldest outstanding group (iter `it`) complete
            __syncthreads();
            if (it + 2 < NKIT) {
                load_stage(sld);
                if (++sld == STAGES) sld = 0;
            }
            CP_COMMIT();

            const uint32_t sA = sb + sidx * STAGE_BYTES;

            #pragma unroll
            for (int ks = 0; ks < 4; ++ks) {
                const uint32_t cbits = (uint32_t)(2 * ks) + (uint32_t)lchk;
                uint32_t a[4][4];
                #pragma unroll
                for (int mti = 0; mti < 4; ++mti)
                    LDSM_X4(a[mti][0], a[mti][1], a[mti][2], a[mti][3],
                            sA + rbA[mti] + ((cbits ^ r7A[mti]) << 4));
                uint32_t b[4][2];
                #pragma unroll
                for (int np = 0; np < 2; ++np) {
                    uint32_t r0, r1, r2, r3;
                    LDSM_X4(r0, r1, r2, r3,
                            sA + rbB[np] + ((cbits ^ r7B[np]) << 4));
                    b[2 * np + 0][0] = r0; b[2 * np + 0][1] = r2;
                    b[2 * np + 1][0] = r1; b[2 * np + 1][1] = r3;
                }
                #pragma unroll
                for (int mti = 0; mti < 4; ++mti)
                    #pragma unroll
                    for (int nti = 0; nti < 4; ++nti)
                        MMA16816(acc[mti][nti], a[mti], b[nti]);
            }
            if (++sidx == STAGES) sidx = 0;
        }
        CP_WAIT0();

        // ---------------- epilogue ----------------
        {
            const int row_base = m0 + wm0;
            const int col_base = n0 + wn0;
            const int r_in = lane >> 2;
            const int c_in = (lane & 3) * 2;

            #pragma unroll
            for (int nti = 0; nti < 4; ++nti) {
                const int c = col_base + nti * 8 + c_in;
                const float2 sc = *(const float2*)(scale + c);
                const float2 bi = *(const float2*)(bias + c);
                #pragma unroll
                for (int mti = 0; mti < 4; ++mti) {
                    const int r0 = row_base + mti * 16 + r_in;
                    float2 v0, v1;
                    v0.x = acc[mti][nti][0] * sc.x + bi.x;
                    v0.y = acc[mti][nti][1] * sc.y + bi.y;
                    v1.x = acc[mti][nti][2] * sc.x + bi.x;
                    v1.y = acc[mti][nti][3] * sc.y + bi.y;
                    *(float2*)(out + (size_t)r0 * N_TOTAL + c)       = v0;
                    *(float2*)(out + (size_t)(r0 + 8) * N_TOTAL + c) = v1;
                }
            }
        }
    }
}

// ---------------- launch ----------------
extern "C" void kernel_launch(void* const* d_in, const int* in_sizes, int n_in,
                              void* d_out, int out_size) {
    const float* x   = (const float*)d_in[0];
    const int*   wp  = (const int*)d_in[1];
    const float* scl = (const float*)d_in[2];
    const float* bia = (const float*)d_in[3];
    float* out = (float*)d_out;

    cudaFuncSetAttribute(k_gemm, cudaFuncAttributeMaxDynamicSharedMemorySize, SMEM_BYTES);

    // fused prep: 8192 convert blocks + 22016 dequant blocks
    k_prep<<<30208, 256>>>(x, wp);
    // persistent GEMM, 2 CTAs/SM
    k_gemm<<<296, NTHREADS, SMEM_BYTES>>>(scl, bia, out);
}